// round 7
// baseline (speedup 1.0000x reference)
#include <cuda_runtime.h>

// Problem constants
#define N_   5000
#define D_   128
#define T_   100
#define K_   20
#define EPSV 1e-8f

// --------- Kernel B tiling: block covers NT x DT x TC of (n, d, t) ---------
#define NT 16
#define DT 16
#define TC 32
#define NTB 256   // 8 warps: wn in {0,1} x wd in {0..3}; warp tile 8n x 8d

// smem: theta [K][NT][TC] f32 (40KB) + phi2 [K][DT/2][TC] f2 (40KB) + evt int2 (1KB)
#define SMEM_TH_F   (K_ * NT * TC)
#define SMEM_PH_F2  (K_ * (DT / 2) * TC)
#define SMEM_B_BYTES (SMEM_TH_F * 4 + SMEM_PH_F2 * 8 + (NT * (DT / 2)) * 8)

// Fallback scratch (only used if harness output layout lacks these regions;
// R6 pass confirmed the layout, so these are normally untouched).
__device__ float g_phip_scratch[K_ * D_ * T_];
__device__ float g_theta_scratch[N_ * K_ * T_];

// ---------------------------------------------------------------------------
// Kernel 1: phi_prob = sigmoid(phi)
// ---------------------------------------------------------------------------
__global__ void sigmoid_kernel(const float4* __restrict__ phi,
                               float4* __restrict__ out) {
    int i = blockIdx.x * blockDim.x + threadIdx.x;
    if (i < (K_ * D_ * T_) / 4) {
        float4 v = phi[i];
        v.x = __fdividef(1.0f, 1.0f + __expf(-v.x));
        v.y = __fdividef(1.0f, 1.0f + __expf(-v.y));
        v.z = __fdividef(1.0f, 1.0f + __expf(-v.z));
        v.w = __fdividef(1.0f, 1.0f + __expf(-v.w));
        out[i] = v;
    }
}

// ---------------------------------------------------------------------------
// Kernel 2: theta = softmax_K(lambda), streaming, one thread per (n,t)
//   consecutive threads -> consecutive t: coalesced 400B runs per k
// ---------------------------------------------------------------------------
__global__ __launch_bounds__(256)
void softmax_kernel(const float* __restrict__ lam,
                    float* __restrict__ theta) {
    int idx = blockIdx.x * 256 + threadIdx.x;
    if (idx >= N_ * T_) return;
    int n = idx / T_;
    int t = idx - n * T_;
    const float* src = lam + n * (K_ * T_) + t;
    float v[K_];
    #pragma unroll
    for (int k = 0; k < K_; ++k) v[k] = src[k * T_];
    float m = v[0];
    #pragma unroll
    for (int k = 1; k < K_; ++k) m = fmaxf(m, v[k]);
    float s = 0.0f;
    #pragma unroll
    for (int k = 0; k < K_; ++k) { v[k] = __expf(v[k] - m); s += v[k]; }
    float inv = __fdividef(1.0f, s);
    float* dst = theta + n * (K_ * T_) + t;
    #pragma unroll
    for (int k = 0; k < K_; ++k) dst[k * T_] = v[k] * inv;
}

// ---------------------------------------------------------------------------
// Kernel 3: pi[n,d,t] = clip(mask * sum_k theta[n,k,t]*phip[k,d,t])
//   grid (D/DT, N/NT, T-tiles): x = d-tile so blocks sharing a theta tile
//   are schedule-adjacent (theta hits L2). 256 thr, 83KB smem, 2 blocks/SM.
// ---------------------------------------------------------------------------
__global__ __launch_bounds__(NTB, 2)
void gemm_kernel(const float* __restrict__ theta_g,
                 const float* __restrict__ phip,
                 const int*   __restrict__ evt,   // int32
                 float*       __restrict__ pi) {
    extern __shared__ float smem[];
    float*  s_th = smem;                                    // [K][NT][TC]
    float2* s_ph = (float2*)(smem + SMEM_TH_F);             // [K][DT/2][TC]
    int2*   s_ev = (int2*)(smem + SMEM_TH_F + SMEM_PH_F2 * 2);  // [NT][DT/2]

    const int tid = threadIdx.x;
    const int d0 = blockIdx.x * DT;
    const int n0 = blockIdx.y * NT;
    const int t0 = blockIdx.z * TC;

    // ---- theta tile: K*NT*TC = 10240 elems, 40 iters ----
    for (int f = tid; f < K_ * NT * TC; f += NTB) {
        int j = f & 31;
        int i = (f >> 5) & (NT - 1);
        int k = f >> 9;                 // / (NT*32)
        int n = n0 + i, t = t0 + j;
        float v = 0.0f;
        if (n < N_ && t < T_) v = theta_g[n * (K_ * T_) + k * T_ + t];
        s_th[(k * NT + i) * TC + j] = v;
    }
    // ---- phi tile as d-paired float2: K*(DT/2)*TC = 5120, 20 iters ----
    for (int f = tid; f < K_ * (DT / 2) * TC; f += NTB) {
        int j  = f & 31;
        int dp = (f >> 5) & (DT / 2 - 1);
        int k  = f >> 8;                // / ((DT/2)*32)
        int t  = t0 + j;
        float2 v = make_float2(0.0f, 0.0f);
        if (t < T_) {
            int base = k * (D_ * T_) + (d0 + 2 * dp) * T_ + t;
            v.x = phip[base];
            v.y = phip[base + T_];
        }
        s_ph[(k * (DT / 2) + dp) * TC + j] = v;
    }
    // ---- event times as int2 pairs ----
    for (int f = tid; f < NT * (DT / 2); f += NTB) {
        int dp = f & (DT / 2 - 1);
        int i  = f / (DT / 2);
        int n  = n0 + i;
        int2 e = make_int2(0, 0);
        if (n < N_)
            e = *reinterpret_cast<const int2*>(evt + (size_t)n * D_ + d0 + 2 * dp);
        s_ev[f] = e;
    }
    __syncthreads();

    // ---- GEMM: warp tile 8n x 4 d-pairs ----
    const int w    = tid >> 5;
    const int lane = tid & 31;     // lane == t
    const int nb   = (w >> 2) * 8; // 0 or 8
    const int dpb  = (w & 3) * 2;  // 0,2,4,6

    unsigned long long acc[8][2];
    #pragma unroll
    for (int i = 0; i < 8; ++i) { acc[i][0] = 0ULL; acc[i][1] = 0ULL; }

    #pragma unroll
    for (int k = 0; k < K_; ++k) {
        unsigned long long a2[8];
        const float* th = &s_th[(k * NT + nb) * TC + lane];
        #pragma unroll
        for (int i = 0; i < 8; ++i) {
            float a = th[i * TC];
            asm("mov.b64 %0, {%1, %1};" : "=l"(a2[i]) : "f"(a));
        }
        unsigned long long b2[2];
        const float2* ph = &s_ph[(k * (DT / 2) + dpb) * TC + lane];
        #pragma unroll
        for (int p = 0; p < 2; ++p)
            b2[p] = *reinterpret_cast<const unsigned long long*>(&ph[p * TC]);
        #pragma unroll
        for (int i = 0; i < 8; ++i)
            #pragma unroll
            for (int p = 0; p < 2; ++p)
                asm("fma.rn.f32x2 %0, %1, %2, %0;"
                    : "+l"(acc[i][p]) : "l"(a2[i]), "l"(b2[p]));
    }

    // ---- epilogue: mask, clip, coalesced stores ----
    const int t  = t0 + lane;
    const bool tv = (t < T_);
    #pragma unroll
    for (int i = 0; i < 8; ++i) {
        int n = n0 + nb + i;
        if (n >= N_) continue;
        float* prow = pi + (size_t)n * (D_ * T_);
        #pragma unroll
        for (int p = 0; p < 2; ++p) {
            float v0, v1;
            asm("mov.b64 {%0, %1}, %2;" : "=f"(v0), "=f"(v1) : "l"(acc[i][p]));
            int2 e = s_ev[(nb + i) * (DT / 2) + dpb + p];
            int  c = (dpb + p) * 2;
            v0 = (t <= e.x) ? v0 : 0.0f;
            v1 = (t <= e.y) ? v1 : 0.0f;
            v0 = fminf(fmaxf(v0, EPSV), 1.0f - EPSV);
            v1 = fminf(fmaxf(v1, EPSV), 1.0f - EPSV);
            if (tv) {
                prow[(d0 + c) * T_ + t]     = v0;   // 128B runs per (n,d)
                prow[(d0 + c + 1) * T_ + t] = v1;
            }
        }
    }
}

// ---------------------------------------------------------------------------
// Launch
// ---------------------------------------------------------------------------
extern "C" void kernel_launch(void* const* d_in, const int* in_sizes, int n_in,
                              void* d_out, int out_size) {
    const float* lam = (const float*)d_in[0];  // [N,K,T] f32
    const float* phi = (const float*)d_in[1];  // [K,D,T] f32
    const int*   evt = (const int*)d_in[2];    // [N,D]   i32

    const long long PI_SZ  = (long long)N_ * D_ * T_;
    const long long TH_SZ  = (long long)N_ * K_ * T_;
    const long long PHP_SZ = (long long)K_ * D_ * T_;

    float* out   = (float*)d_out;
    float* pi    = out;
    float* theta = out + PI_SZ;
    float* phip  = out + PI_SZ + TH_SZ;

    const long long osz = (long long)out_size;
    if (osz < PI_SZ + TH_SZ) {          // fallback: theta region missing
        cudaGetSymbolAddress((void**)&theta, g_theta_scratch);
    }
    if (osz < PI_SZ + TH_SZ + PHP_SZ) { // fallback: phi_prob region missing
        cudaGetSymbolAddress((void**)&phip, g_phip_scratch);
    }

    // 1) phi_prob = sigmoid(phi)
    int nvec = (K_ * D_ * T_) / 4;
    sigmoid_kernel<<<(nvec + 255) / 256, 256>>>((const float4*)phi,
                                                (float4*)phip);

    // 2) theta = softmax(lambda)
    int npts = N_ * T_;
    softmax_kernel<<<(npts + 255) / 256, 256>>>(lam, theta);

    // 3) pi = mask*clip(theta @ phi_prob)
    cudaFuncSetAttribute(gemm_kernel,
                         cudaFuncAttributeMaxDynamicSharedMemorySize,
                         SMEM_B_BYTES);
    dim3 grid(D_ / DT, (N_ + NT - 1) / NT, (T_ + TC - 1) / TC);  // 8 x 313 x 4
    gemm_kernel<<<grid, NTB, SMEM_B_BYTES>>>(theta, phip, evt, pi);
}

// round 9
// speedup vs baseline: 2.7002x; 2.7002x over previous
#include <cuda_runtime.h>

// Problem constants
#define N_   5000
#define D_   128
#define T_   100
#define K_   20
#define EPSV 1e-8f

// GEMM kernel tiling: persistent-over-n block on a (DT x TC) cell
#define NT 16          // n per step
#define DT 16          // d per block (8 float2 pairs)
#define TC 32          // t per block (= warp lanes)
#define NTB 256        // 8 warps: 4 n-groups x 2 pair-groups
#define NTILES   313   // ceil(5000/16)
#define ZSPLIT   9     // grid.z; 8*4*9 = 288 blocks ~ one wave @ 2/SM
#define STEPS    35    // ceil(313/9)

// smem: theta [K][NT][TC] f32 + phi2 [K][DT/2][TC] f2 + evt [NT][DT/2] int2
#define SMEM_TH_F   (K_ * NT * TC)                  // 10240 f
#define SMEM_PH_F2  (K_ * (DT / 2) * TC)            // 5120 f2
#define SMEM_BYTES  (SMEM_TH_F * 4 + SMEM_PH_F2 * 8 + (NT * (DT / 2)) * 8)

__device__ float g_phip_scratch[K_ * D_ * T_];
__device__ float g_theta_scratch[N_ * K_ * T_];

// ---------------------------------------------------------------------------
// Kernel 1: phi_prob = sigmoid(phi)
// ---------------------------------------------------------------------------
__global__ void sigmoid_kernel(const float4* __restrict__ phi,
                               float4* __restrict__ out) {
    int i = blockIdx.x * blockDim.x + threadIdx.x;
    if (i < (K_ * D_ * T_) / 4) {
        float4 v = phi[i];
        v.x = __fdividef(1.0f, 1.0f + __expf(-v.x));
        v.y = __fdividef(1.0f, 1.0f + __expf(-v.y));
        v.z = __fdividef(1.0f, 1.0f + __expf(-v.z));
        v.w = __fdividef(1.0f, 1.0f + __expf(-v.w));
        out[i] = v;
    }
}

// ---------------------------------------------------------------------------
// Kernel 2: theta = softmax_K(lambda), one thread per (n,t), coalesced in t
// ---------------------------------------------------------------------------
__global__ __launch_bounds__(256)
void softmax_kernel(const float* __restrict__ lam,
                    float* __restrict__ theta) {
    int idx = blockIdx.x * 256 + threadIdx.x;
    if (idx >= N_ * T_) return;
    int n = idx / T_;
    int t = idx - n * T_;
    const float* src = lam + n * (K_ * T_) + t;
    float v[K_];
    #pragma unroll
    for (int k = 0; k < K_; ++k) v[k] = src[k * T_];
    float m = v[0];
    #pragma unroll
    for (int k = 1; k < K_; ++k) m = fmaxf(m, v[k]);
    float s = 0.0f;
    #pragma unroll
    for (int k = 0; k < K_; ++k) { v[k] = __expf(v[k] - m); s += v[k]; }
    float inv = __fdividef(1.0f, s);
    float* dst = theta + n * (K_ * T_) + t;
    #pragma unroll
    for (int k = 0; k < K_; ++k) dst[k * T_] = v[k] * inv;
}

// ---------------------------------------------------------------------------
// Kernel 3: pi = clip(mask * (theta @ phi_prob))
//   Block persists on (d-tile, t-chunk), loops over n-tiles:
//   phi tile loaded ONCE; per-step theta tile via 10x LDG.128 (L2-resident).
// ---------------------------------------------------------------------------
__global__ __launch_bounds__(NTB, 2)
void gemm_kernel(const float* __restrict__ theta_g,
                 const float* __restrict__ phip,
                 const int*   __restrict__ evt,
                 float*       __restrict__ pi) {
    extern __shared__ float smem[];
    float*  s_th = smem;                                      // [K][NT][TC]
    float2* s_ph = (float2*)(smem + SMEM_TH_F);               // [K][DT/2][TC]
    int2*   s_ev = (int2*)(smem + SMEM_TH_F + SMEM_PH_F2 * 2);// [NT][DT/2]

    const int tid = threadIdx.x;
    const int d0 = blockIdx.x * DT;
    const int t0 = blockIdx.y * TC;

    // ---- phi tile: load once. 20k x 8dp x 8 float4-cols = 1280 units ----
    #pragma unroll
    for (int r = 0; r < 5; ++r) {
        int f  = tid + r * NTB;          // 0..1279
        int j  = f & 7;
        int dp = (f >> 3) & 7;
        int k  = f >> 6;                 // 0..19
        int t  = t0 + 4 * j;
        float4 a = make_float4(0.f, 0.f, 0.f, 0.f);
        float4 b = a;
        if (t < T_) {
            const float* base = phip + k * (D_ * T_) + (d0 + 2 * dp) * T_ + t;
            a = *reinterpret_cast<const float4*>(base);
            b = *reinterpret_cast<const float4*>(base + T_);
        }
        float2* dst = &s_ph[(k * (DT / 2) + dp) * TC + 4 * j];
        dst[0] = make_float2(a.x, b.x);
        dst[1] = make_float2(a.y, b.y);
        dst[2] = make_float2(a.z, b.z);
        dst[3] = make_float2(a.w, b.w);
    }

    const int w    = tid >> 5;
    const int lane = tid & 31;       // lane == t
    const int nb   = (w >> 1) * 4;   // n rows base: 0,4,8,12
    const int pb   = (w & 1) * 4;    // d-pair base: 0 or 4
    const int t    = t0 + lane;
    const bool tv  = (t < T_);

    // ---- loop over n-tiles ----
    for (int s = 0; s < STEPS; ++s) {
        int nt = blockIdx.z * STEPS + s;
        if (nt >= NTILES) break;
        int n0 = nt * NT;

        __syncthreads();   // previous GEMM reads done before refill

        // theta tile: 20k x 16n x 8 float4-cols = 2560 units, 10/thread
        #pragma unroll
        for (int r = 0; r < 10; ++r) {
            int f  = tid + r * NTB;      // 0..2559
            int j  = f & 7;
            int ni = (f >> 3) & 15;
            int k  = f >> 7;             // 0..19
            int tt = t0 + 4 * j;
            int n  = n0 + ni;
            float4 v = make_float4(0.f, 0.f, 0.f, 0.f);
            if (n < N_ && tt < T_)
                v = *reinterpret_cast<const float4*>(
                        theta_g + n * (K_ * T_) + k * T_ + tt);
            *reinterpret_cast<float4*>(&s_th[(k * NT + ni) * TC + 4 * j]) = v;
        }
        // event-time tile: 16n x 8 int2
        if (tid < NT * (DT / 2)) {
            int dp = tid & 7;
            int i  = tid >> 3;
            int n  = n0 + i;
            int2 e = make_int2(0, 0);
            if (n < N_)
                e = *reinterpret_cast<const int2*>(
                        evt + (size_t)n * D_ + d0 + 2 * dp);
            s_ev[i * (DT / 2) + dp] = e;
        }
        __syncthreads();

        // ---- GEMM: 4n x 4 d-pairs per thread ----
        unsigned long long acc[4][4];
        #pragma unroll
        for (int i = 0; i < 4; ++i)
            #pragma unroll
            for (int p = 0; p < 4; ++p) acc[i][p] = 0ULL;

        #pragma unroll
        for (int k = 0; k < K_; ++k) {
            unsigned long long a2[4];
            const float* th = &s_th[(k * NT + nb) * TC + lane];
            #pragma unroll
            for (int i = 0; i < 4; ++i) {
                float a = th[i * TC];
                asm("mov.b64 %0, {%1, %1};" : "=l"(a2[i]) : "f"(a));
            }
            unsigned long long b2[4];
            const float2* ph = &s_ph[(k * (DT / 2) + pb) * TC + lane];
            #pragma unroll
            for (int p = 0; p < 4; ++p)
                b2[p] = *reinterpret_cast<const unsigned long long*>(&ph[p * TC]);
            #pragma unroll
            for (int i = 0; i < 4; ++i)
                #pragma unroll
                for (int p = 0; p < 4; ++p)
                    asm("fma.rn.f32x2 %0, %1, %2, %0;"
                        : "+l"(acc[i][p]) : "l"(a2[i]), "l"(b2[p]));
        }

        // ---- epilogue: mask, clip, coalesced 128B stores ----
        #pragma unroll
        for (int i = 0; i < 4; ++i) {
            int n = n0 + nb + i;
            if (n >= N_) continue;
            float* prow = pi + (size_t)n * (D_ * T_);
            #pragma unroll
            for (int p = 0; p < 4; ++p) {
                float v0, v1;
                asm("mov.b64 {%0, %1}, %2;" : "=f"(v0), "=f"(v1)
                    : "l"(acc[i][p]));
                int2 e = s_ev[(nb + i) * (DT / 2) + pb + p];
                int  c = (pb + p) * 2;
                v0 = (t <= e.x) ? v0 : 0.0f;
                v1 = (t <= e.y) ? v1 : 0.0f;
                v0 = fminf(fmaxf(v0, EPSV), 1.0f - EPSV);
                v1 = fminf(fmaxf(v1, EPSV), 1.0f - EPSV);
                if (tv) {
                    prow[(d0 + c) * T_ + t]     = v0;
                    prow[(d0 + c + 1) * T_ + t] = v1;
                }
            }
        }
    }
}

// ---------------------------------------------------------------------------
// Launch
// ---------------------------------------------------------------------------
extern "C" void kernel_launch(void* const* d_in, const int* in_sizes, int n_in,
                              void* d_out, int out_size) {
    const float* lam = (const float*)d_in[0];  // [N,K,T] f32
    const float* phi = (const float*)d_in[1];  // [K,D,T] f32
    const int*   evt = (const int*)d_in[2];    // [N,D]   i32

    const long long PI_SZ  = (long long)N_ * D_ * T_;
    const long long TH_SZ  = (long long)N_ * K_ * T_;
    const long long PHP_SZ = (long long)K_ * D_ * T_;

    float* out   = (float*)d_out;
    float* pi    = out;
    float* theta = out + PI_SZ;
    float* phip  = out + PI_SZ + TH_SZ;

    const long long osz = (long long)out_size;
    if (osz < PI_SZ + TH_SZ)
        cudaGetSymbolAddress((void**)&theta, g_theta_scratch);
    if (osz < PI_SZ + TH_SZ + PHP_SZ)
        cudaGetSymbolAddress((void**)&phip, g_phip_scratch);

    // 1) phi_prob = sigmoid(phi)
    int nvec = (K_ * D_ * T_) / 4;
    sigmoid_kernel<<<(nvec + 255) / 256, 256>>>((const float4*)phi,
                                                (float4*)phip);

    // 2) theta = softmax(lambda)
    int npts = N_ * T_;
    softmax_kernel<<<(npts + 255) / 256, 256>>>(lam, theta);

    // 3) pi = mask*clip(theta @ phi_prob)
    cudaFuncSetAttribute(gemm_kernel,
                         cudaFuncAttributeMaxDynamicSharedMemorySize,
                         SMEM_BYTES);
    dim3 grid(D_ / DT, (T_ + TC - 1) / TC, ZSPLIT);  // 8 x 4 x 9 = 288
    gemm_kernel<<<grid, NTB, SMEM_BYTES>>>(theta, phip, evt, pi);
}

// round 10
// speedup vs baseline: 2.9761x; 1.1022x over previous
#include <cuda_runtime.h>

// Problem constants
#define N_   5000
#define D_   128
#define T_   100
#define K_   20
#define EPSV 1e-8f

// GEMM kernel tiling: persistent-over-n block on a (DT x TC) cell
#define NT 16          // n per step
#define DT 16          // d per block (8 float2 pairs)
#define TC 32          // t per block (= warp lanes)
#define NTB 256        // 8 warps: 4 n-groups x 2 pair-groups
#define NTILES   313   // ceil(5000/16)
#define ZSPLIT   9     // grid.z; 8*4*9 = 288 blocks ~ one wave @ 2/SM
#define STEPS    35    // ceil(313/9)
#define KT_      (K_ * T_)

// smem: theta [K][NT][TC] f32 + phi2 [K][DT/2][TC] f2 + evt [NT][DT/2] int2
#define SMEM_TH_F   (K_ * NT * TC)                  // 10240 f
#define SMEM_PH_F2  (K_ * (DT / 2) * TC)            // 5120 f2
#define SMEM_BYTES  (SMEM_TH_F * 4 + SMEM_PH_F2 * 8 + (NT * (DT / 2)) * 8)

__device__ float g_phip_scratch[K_ * D_ * T_];
__device__ float g_theta_scratch[N_ * K_ * T_];

// ---------------------------------------------------------------------------
// Kernel 1: phi_prob = sigmoid(phi)
// ---------------------------------------------------------------------------
__global__ void sigmoid_kernel(const float4* __restrict__ phi,
                               float4* __restrict__ out) {
    int i = blockIdx.x * blockDim.x + threadIdx.x;
    if (i < (K_ * D_ * T_) / 4) {
        float4 v = phi[i];
        v.x = __fdividef(1.0f, 1.0f + __expf(-v.x));
        v.y = __fdividef(1.0f, 1.0f + __expf(-v.y));
        v.z = __fdividef(1.0f, 1.0f + __expf(-v.z));
        v.w = __fdividef(1.0f, 1.0f + __expf(-v.w));
        out[i] = v;
    }
}

// ---------------------------------------------------------------------------
// Kernel 2: theta = softmax_K(lambda), one thread per (n,t), coalesced in t
// ---------------------------------------------------------------------------
__global__ __launch_bounds__(256)
void softmax_kernel(const float* __restrict__ lam,
                    float* __restrict__ theta) {
    int idx = blockIdx.x * 256 + threadIdx.x;
    if (idx >= N_ * T_) return;
    int n = idx / T_;
    int t = idx - n * T_;
    const float* src = lam + n * KT_ + t;
    float v[K_];
    #pragma unroll
    for (int k = 0; k < K_; ++k) v[k] = src[k * T_];
    float m = v[0];
    #pragma unroll
    for (int k = 1; k < K_; ++k) m = fmaxf(m, v[k]);
    float s = 0.0f;
    #pragma unroll
    for (int k = 0; k < K_; ++k) { v[k] = __expf(v[k] - m); s += v[k]; }
    float inv = __fdividef(1.0f, s);
    float* dst = theta + n * KT_ + t;
    #pragma unroll
    for (int k = 0; k < K_; ++k) dst[k * T_] = v[k] * inv;
}

// ---------------------------------------------------------------------------
// Kernel 3: pi = clip(mask * (theta @ phi_prob))
//   Persistent block on (d-tile, t-chunk); phi loaded once; theta tiles
//   software-pipelined through registers (prefetch next during GEMM).
// ---------------------------------------------------------------------------
__global__ __launch_bounds__(NTB, 2)
void gemm_kernel(const float* __restrict__ theta_g,
                 const float* __restrict__ phip,
                 const int*   __restrict__ evt,
                 float*       __restrict__ pi) {
    extern __shared__ float smem[];
    float*  s_th = smem;                                      // [K][NT][TC]
    float2* s_ph = (float2*)(smem + SMEM_TH_F);               // [K][DT/2][TC]
    int2*   s_ev = (int2*)(smem + SMEM_TH_F + SMEM_PH_F2 * 2);// [NT][DT/2]

    const int tid = threadIdx.x;
    const int d0 = blockIdx.x * DT;
    const int t0 = blockIdx.y * TC;

    // ---- phi tile: load once ----
    #pragma unroll
    for (int r = 0; r < 5; ++r) {
        int f  = tid + r * NTB;          // 0..1279
        int j  = f & 7;
        int dp = (f >> 3) & 7;
        int k  = f >> 6;                 // 0..19
        int t  = t0 + 4 * j;
        float4 a = make_float4(0.f, 0.f, 0.f, 0.f);
        float4 b = a;
        if (t < T_) {
            const float* base = phip + k * (D_ * T_) + (d0 + 2 * dp) * T_ + t;
            a = *reinterpret_cast<const float4*>(base);
            b = *reinterpret_cast<const float4*>(base + T_);
        }
        float2* dst = &s_ph[(k * (DT / 2) + dp) * TC + 4 * j];
        dst[0] = make_float2(a.x, b.x);
        dst[1] = make_float2(a.y, b.y);
        dst[2] = make_float2(a.z, b.z);
        dst[3] = make_float2(a.w, b.w);
    }

    // ---- per-thread theta prefetch descriptors (n0-invariant parts) ----
    int   off_[10];    // ni*KT + k*T + tt
    int   ni_[10];
    bool  tv_[10];
    float4* sdst_[10];
    #pragma unroll
    for (int r = 0; r < 10; ++r) {
        int f  = tid + r * NTB;          // 0..2559
        int j  = f & 7;
        int ni = (f >> 3) & 15;
        int k  = f >> 7;                 // 0..19
        int tt = t0 + 4 * j;
        off_[r] = ni * KT_ + k * T_ + tt;
        ni_[r]  = ni;
        tv_[r]  = (tt < T_);
        sdst_[r] = reinterpret_cast<float4*>(&s_th[(k * NT + ni) * TC + 4 * j]);
    }
    // evt prefetch descriptor (threads 0..127)
    const bool eact = (tid < NT * (DT / 2));
    const int  edp  = tid & 7;
    const int  eni  = tid >> 3;

    const int w    = tid >> 5;
    const int lane = tid & 31;       // lane == t
    const int nb   = (w >> 1) * 4;   // n rows base: 0,4,8,12
    const int pb   = (w & 1) * 4;    // d-pair base: 0 or 4
    const int t    = t0 + lane;
    const bool tvl = (t < T_);

    // ---- prefetch first theta tile + evt into registers ----
    const int n0_first = blockIdx.z * STEPS * NT;
    float4 pf[10];
    #pragma unroll
    for (int r = 0; r < 10; ++r) {
        pf[r] = make_float4(0.f, 0.f, 0.f, 0.f);
        if (n0_first + ni_[r] < N_ && tv_[r])
            pf[r] = *reinterpret_cast<const float4*>(
                        theta_g + n0_first * KT_ + off_[r]);
    }
    int2 pe = make_int2(0, 0);
    if (eact && n0_first + eni < N_)
        pe = *reinterpret_cast<const int2*>(
                 evt + (size_t)(n0_first + eni) * D_ + d0 + 2 * edp);

    // ---- main loop over n-tiles ----
    for (int s = 0; s < STEPS; ++s) {
        int nt = blockIdx.z * STEPS + s;
        if (nt >= NTILES) break;
        int n0 = nt * NT;

        __syncthreads();   // prior GEMM done reading smem

        // commit prefetched tile to smem
        #pragma unroll
        for (int r = 0; r < 10; ++r) *sdst_[r] = pf[r];
        if (eact) s_ev[eni * (DT / 2) + edp] = pe;
        __syncthreads();

        // prefetch NEXT tile (latency overlapped with GEMM below)
        {
            int n0n = n0 + NT;
            #pragma unroll
            for (int r = 0; r < 10; ++r) {
                pf[r] = make_float4(0.f, 0.f, 0.f, 0.f);
                if (n0n + ni_[r] < N_ && tv_[r])
                    pf[r] = *reinterpret_cast<const float4*>(
                                theta_g + n0n * KT_ + off_[r]);
            }
            pe = make_int2(0, 0);
            if (eact && n0n + eni < N_)
                pe = *reinterpret_cast<const int2*>(
                         evt + (size_t)(n0n + eni) * D_ + d0 + 2 * edp);
        }

        // ---- GEMM: 4n x 4 d-pairs per thread ----
        unsigned long long acc[4][4];
        #pragma unroll
        for (int i = 0; i < 4; ++i)
            #pragma unroll
            for (int p = 0; p < 4; ++p) acc[i][p] = 0ULL;

        #pragma unroll
        for (int k = 0; k < K_; ++k) {
            unsigned long long a2[4];
            const float* th = &s_th[(k * NT + nb) * TC + lane];
            #pragma unroll
            for (int i = 0; i < 4; ++i) {
                float a = th[i * TC];
                asm("mov.b64 %0, {%1, %1};" : "=l"(a2[i]) : "f"(a));
            }
            unsigned long long b2[4];
            const float2* ph = &s_ph[(k * (DT / 2) + pb) * TC + lane];
            #pragma unroll
            for (int p = 0; p < 4; ++p)
                b2[p] = *reinterpret_cast<const unsigned long long*>(&ph[p * TC]);
            #pragma unroll
            for (int i = 0; i < 4; ++i)
                #pragma unroll
                for (int p = 0; p < 4; ++p)
                    asm("fma.rn.f32x2 %0, %1, %2, %0;"
                        : "+l"(acc[i][p]) : "l"(a2[i]), "l"(b2[p]));
        }

        // ---- epilogue: mask, clip, coalesced 128B stores ----
        #pragma unroll
        for (int i = 0; i < 4; ++i) {
            int n = n0 + nb + i;
            if (n >= N_) continue;
            float* prow = pi + (size_t)n * (D_ * T_);
            #pragma unroll
            for (int p = 0; p < 4; ++p) {
                float v0, v1;
                asm("mov.b64 {%0, %1}, %2;" : "=f"(v0), "=f"(v1)
                    : "l"(acc[i][p]));
                int2 e = s_ev[(nb + i) * (DT / 2) + pb + p];
                int  c = (pb + p) * 2;
                v0 = (t <= e.x) ? v0 : 0.0f;
                v1 = (t <= e.y) ? v1 : 0.0f;
                v0 = fminf(fmaxf(v0, EPSV), 1.0f - EPSV);
                v1 = fminf(fmaxf(v1, EPSV), 1.0f - EPSV);
                if (tvl) {
                    prow[(d0 + c) * T_ + t]     = v0;
                    prow[(d0 + c + 1) * T_ + t] = v1;
                }
            }
        }
    }
}

// ---------------------------------------------------------------------------
// Launch
// ---------------------------------------------------------------------------
extern "C" void kernel_launch(void* const* d_in, const int* in_sizes, int n_in,
                              void* d_out, int out_size) {
    const float* lam = (const float*)d_in[0];  // [N,K,T] f32
    const float* phi = (const float*)d_in[1];  // [K,D,T] f32
    const int*   evt = (const int*)d_in[2];    // [N,D]   i32

    const long long PI_SZ  = (long long)N_ * D_ * T_;
    const long long TH_SZ  = (long long)N_ * K_ * T_;
    const long long PHP_SZ = (long long)K_ * D_ * T_;

    float* out   = (float*)d_out;
    float* pi    = out;
    float* theta = out + PI_SZ;
    float* phip  = out + PI_SZ + TH_SZ;

    const long long osz = (long long)out_size;
    if (osz < PI_SZ + TH_SZ)
        cudaGetSymbolAddress((void**)&theta, g_theta_scratch);
    if (osz < PI_SZ + TH_SZ + PHP_SZ)
        cudaGetSymbolAddress((void**)&phip, g_phip_scratch);

    // 1) phi_prob = sigmoid(phi)
    int nvec = (K_ * D_ * T_) / 4;
    sigmoid_kernel<<<(nvec + 255) / 256, 256>>>((const float4*)phi,
                                                (float4*)phip);

    // 2) theta = softmax(lambda)
    int npts = N_ * T_;
    softmax_kernel<<<(npts + 255) / 256, 256>>>(lam, theta);

    // 3) pi = mask*clip(theta @ phi_prob)
    cudaFuncSetAttribute(gemm_kernel,
                         cudaFuncAttributeMaxDynamicSharedMemorySize,
                         SMEM_BYTES);
    dim3 grid(D_ / DT, (T_ + TC - 1) / TC, ZSPLIT);  // 8 x 4 x 9 = 288
    gemm_kernel<<<grid, NTB, SMEM_BYTES>>>(theta, phip, evt, pi);
}

// round 12
// speedup vs baseline: 3.0980x; 1.0409x over previous
#include <cuda_runtime.h>
#include <cstdint>

// Problem constants
#define N_   5000
#define D_   128
#define T_   100
#define K_   20
#define KH   10            // half-K for pipeline granularity
#define EPSV 1e-8f
#define KT_  (K_ * T_)

// GEMM tiling
#define NT 16
#define DT 16
#define TC 32
#define NTB 256
#define NTILES 313         // ceil(5000/16)
#define ZSPLIT 9           // 8 x 4 x 9 = 288 blocks = one wave @ 2/SM
#define STEPS  35          // ceil(313/9)

// smem (floats): thA[KH][NT][TC] + thB[KH][NT][TC] + ph[K][DT/2][TC]f2 + ev
#define TH_HALF_F  (KH * NT * TC)           // 5120
#define PH_F2      (K_ * (DT / 2) * TC)     // 5120 float2
#define SMEM_BYTES (TH_HALF_F * 4 * 2 + PH_F2 * 8 + NT * (DT / 2) * 8)

__device__ float g_phip_scratch[K_ * D_ * T_];
__device__ float g_theta_scratch[N_ * K_ * T_];

// ---- cp.async helpers ----
__device__ __forceinline__ void cpa16(uint32_t d, const float* s, bool p) {
    asm volatile("cp.async.cg.shared.global [%0], [%1], 16, %2;"
                 :: "r"(d), "l"(s), "r"(p ? 16 : 0));
}
__device__ __forceinline__ void cpa8(uint32_t d, const int* s, bool p) {
    asm volatile("cp.async.ca.shared.global [%0], [%1], 8, %2;"
                 :: "r"(d), "l"(s), "r"(p ? 8 : 0));
}
#define CPCOMMIT() asm volatile("cp.async.commit_group;")
#define CPWAIT0()  asm volatile("cp.async.wait_group 0;")

// ---------------------------------------------------------------------------
// Kernel 1: phi_prob = sigmoid(phi)
// ---------------------------------------------------------------------------
__global__ void sigmoid_kernel(const float4* __restrict__ phi,
                               float4* __restrict__ out) {
    int i = blockIdx.x * blockDim.x + threadIdx.x;
    if (i < (K_ * D_ * T_) / 4) {
        float4 v = phi[i];
        v.x = __fdividef(1.0f, 1.0f + __expf(-v.x));
        v.y = __fdividef(1.0f, 1.0f + __expf(-v.y));
        v.z = __fdividef(1.0f, 1.0f + __expf(-v.z));
        v.w = __fdividef(1.0f, 1.0f + __expf(-v.w));
        out[i] = v;
    }
}

// ---------------------------------------------------------------------------
// Kernel 2: theta = softmax_K(lambda)
// ---------------------------------------------------------------------------
__global__ __launch_bounds__(256)
void softmax_kernel(const float* __restrict__ lam,
                    float* __restrict__ theta) {
    int idx = blockIdx.x * 256 + threadIdx.x;
    if (idx >= N_ * T_) return;
    int n = idx / T_;
    int t = idx - n * T_;
    const float* src = lam + n * KT_ + t;
    float v[K_];
    #pragma unroll
    for (int k = 0; k < K_; ++k) v[k] = src[k * T_];
    float m = v[0];
    #pragma unroll
    for (int k = 1; k < K_; ++k) m = fmaxf(m, v[k]);
    float s = 0.0f;
    #pragma unroll
    for (int k = 0; k < K_; ++k) { v[k] = __expf(v[k] - m); s += v[k]; }
    float inv = __fdividef(1.0f, s);
    float* dst = theta + n * KT_ + t;
    #pragma unroll
    for (int k = 0; k < K_; ++k) dst[k * T_] = v[k] * inv;
}

// ---------------------------------------------------------------------------
// Kernel 3: pi = clip(mask * (theta @ phi_prob))
//   Persistent block; phi loaded once; theta half-K tiles streamed by
//   cp.async into two half-buffers (A: k<10, B: k>=10) — HW pipeline,
//   zero prefetch registers. pi stored with .cs (L2 evict-first).
// ---------------------------------------------------------------------------
__global__ __launch_bounds__(NTB, 2)
void gemm_kernel(const float* __restrict__ theta_g,
                 const float* __restrict__ phip,
                 const int*   __restrict__ evt,
                 float*       __restrict__ pi) {
    extern __shared__ float smem[];
    float*  s_thA = smem;                                   // [KH][NT][TC]
    float*  s_thB = smem + TH_HALF_F;                       // [KH][NT][TC]
    float2* s_ph  = (float2*)(smem + 2 * TH_HALF_F);        // [K][DT/2][TC]
    int2*   s_ev  = (int2*)(smem + 2 * TH_HALF_F + PH_F2 * 2); // [NT][DT/2]

    const uint32_t u_thA = (uint32_t)__cvta_generic_to_shared(s_thA);
    const uint32_t u_thB = (uint32_t)__cvta_generic_to_shared(s_thB);
    const uint32_t u_ev  = (uint32_t)__cvta_generic_to_shared(s_ev);

    const int tid = threadIdx.x;
    const int d0 = blockIdx.x * DT;
    const int t0 = blockIdx.y * TC;

    // ---- phi tile: load once (pairs of d interleaved as float2) ----
    #pragma unroll
    for (int r = 0; r < 5; ++r) {
        int f  = tid + r * NTB;          // 0..1279
        int j  = f & 7;
        int dp = (f >> 3) & 7;
        int k  = f >> 6;                 // 0..19
        int t  = t0 + 4 * j;
        float4 a = make_float4(0.f, 0.f, 0.f, 0.f);
        float4 b = a;
        if (t < T_) {
            const float* base = phip + k * (D_ * T_) + (d0 + 2 * dp) * T_ + t;
            a = *reinterpret_cast<const float4*>(base);
            b = *reinterpret_cast<const float4*>(base + T_);
        }
        float2* dst = &s_ph[(k * (DT / 2) + dp) * TC + 4 * j];
        dst[0] = make_float2(a.x, b.x);
        dst[1] = make_float2(a.y, b.y);
        dst[2] = make_float2(a.z, b.z);
        dst[3] = make_float2(a.w, b.w);
    }

    // ---- theta cp.async descriptors (5 float4 per thread per half) ----
    int      cni[5];        // n offset within tile
    int      coff[5];       // ni*KT + kk*T + (t0+4j)  (k-half A basis)
    uint32_t cdst[5];       // dst within half buffer
    bool     ctv[5];
    #pragma unroll
    for (int r = 0; r < 5; ++r) {
        int f  = tid + r * NTB;          // 0..1279
        int j  = f & 7;
        int ni = (f >> 3) & 15;
        int kk = f >> 7;                 // 0..9
        int tt = t0 + 4 * j;
        cni[r]  = ni;
        ctv[r]  = (tt < T_);
        coff[r] = ni * KT_ + kk * T_ + tt;
        cdst[r] = ((kk * NT + ni) * TC + 4 * j) * 4;
    }
    const bool eact = (tid < NT * (DT / 2));
    const int  edp  = tid & 7;
    const int  eni  = tid >> 3;

    const int w    = tid >> 5;
    const int lane = tid & 31;       // lane == t
    const int nb   = (w >> 1) * 4;   // 0,4,8,12
    const int pb   = (w & 1) * 4;    // 0 or 4
    const int t    = t0 + lane;
    const bool tvl = (t < T_);

    // ---- prologue: issue A(s=0) ----
    {
        int n0 = blockIdx.z * STEPS * NT;
        #pragma unroll
        for (int r = 0; r < 5; ++r)
            cpa16(u_thA + cdst[r], theta_g + n0 * KT_ + coff[r],
                  (n0 + cni[r] < N_) && ctv[r]);
        CPCOMMIT();
    }

    for (int s = 0; s < STEPS; ++s) {
        int nt = blockIdx.z * STEPS + s;
        if (nt >= NTILES) break;
        int n0 = nt * NT;

        CPWAIT0();           // A(s) ready
        __syncthreads();     // + prior gemm-B done reading B buffer

        // issue B(s) (theta k=10..19) + evt(s)
        #pragma unroll
        for (int r = 0; r < 5; ++r)
            cpa16(u_thB + cdst[r], theta_g + n0 * KT_ + coff[r] + KH * T_,
                  (n0 + cni[r] < N_) && ctv[r]);
        if (eact)
            cpa8(u_ev + (eni * (DT / 2) + edp) * 8,
                 evt + (size_t)(n0 + eni) * D_ + d0 + 2 * edp,
                 n0 + eni < N_);
        CPCOMMIT();

        unsigned long long acc[4][4];
        #pragma unroll
        for (int i = 0; i < 4; ++i)
            #pragma unroll
            for (int p = 0; p < 4; ++p) acc[i][p] = 0ULL;

        // ---- GEMM half A: k = 0..9 ----
        #pragma unroll
        for (int kh = 0; kh < KH; ++kh) {
            unsigned long long a2[4];
            const float* th = &s_thA[(kh * NT + nb) * TC + lane];
            #pragma unroll
            for (int i = 0; i < 4; ++i) {
                float a = th[i * TC];
                asm("mov.b64 %0, {%1, %1};" : "=l"(a2[i]) : "f"(a));
            }
            unsigned long long b2[4];
            const float2* ph = &s_ph[(kh * (DT / 2) + pb) * TC + lane];
            #pragma unroll
            for (int p = 0; p < 4; ++p)
                b2[p] = *reinterpret_cast<const unsigned long long*>(&ph[p * TC]);
            #pragma unroll
            for (int i = 0; i < 4; ++i)
                #pragma unroll
                for (int p = 0; p < 4; ++p)
                    asm("fma.rn.f32x2 %0, %1, %2, %0;"
                        : "+l"(acc[i][p]) : "l"(a2[i]), "l"(b2[p]));
        }

        CPWAIT0();           // B(s) + evt ready
        __syncthreads();     // all warps done with A buffer

        // issue A(s+1)
        {
            int n0n = n0 + NT;
            #pragma unroll
            for (int r = 0; r < 5; ++r)
                cpa16(u_thA + cdst[r], theta_g + n0n * KT_ + coff[r],
                      (n0n + cni[r] < N_) && ctv[r]);
            CPCOMMIT();
        }

        // ---- GEMM half B: k = 10..19 ----
        #pragma unroll
        for (int kh = 0; kh < KH; ++kh) {
            unsigned long long a2[4];
            const float* th = &s_thB[(kh * NT + nb) * TC + lane];
            #pragma unroll
            for (int i = 0; i < 4; ++i) {
                float a = th[i * TC];
                asm("mov.b64 %0, {%1, %1};" : "=l"(a2[i]) : "f"(a));
            }
            unsigned long long b2[4];
            const float2* ph = &s_ph[((KH + kh) * (DT / 2) + pb) * TC + lane];
            #pragma unroll
            for (int p = 0; p < 4; ++p)
                b2[p] = *reinterpret_cast<const unsigned long long*>(&ph[p * TC]);
            #pragma unroll
            for (int i = 0; i < 4; ++i)
                #pragma unroll
                for (int p = 0; p < 4; ++p)
                    asm("fma.rn.f32x2 %0, %1, %2, %0;"
                        : "+l"(acc[i][p]) : "l"(a2[i]), "l"(b2[p]));
        }

        // ---- epilogue: mask, clip, streaming stores ----
        #pragma unroll
        for (int i = 0; i < 4; ++i) {
            int n = n0 + nb + i;
            if (n >= N_) continue;
            float* prow = pi + (size_t)n * (D_ * T_);
            #pragma unroll
            for (int p = 0; p < 4; ++p) {
                float v0, v1;
                asm("mov.b64 {%0, %1}, %2;" : "=f"(v0), "=f"(v1)
                    : "l"(acc[i][p]));
                int2 e = s_ev[(nb + i) * (DT / 2) + pb + p];
                int  c = (pb + p) * 2;
                v0 = (t <= e.x) ? v0 : 0.0f;
                v1 = (t <= e.y) ? v1 : 0.0f;
                v0 = fminf(fmaxf(v0, EPSV), 1.0f - EPSV);
                v1 = fminf(fmaxf(v1, EPSV), 1.0f - EPSV);
                if (tvl) {
                    __stcs(&prow[(d0 + c) * T_ + t], v0);
                    __stcs(&prow[(d0 + c + 1) * T_ + t], v1);
                }
            }
        }
    }
    CPWAIT0();   // drain any stray prefetch before CTA exit
}

// ---------------------------------------------------------------------------
// Launch
// ---------------------------------------------------------------------------
extern "C" void kernel_launch(void* const* d_in, const int* in_sizes, int n_in,
                              void* d_out, int out_size) {
    const float* lam = (const float*)d_in[0];  // [N,K,T] f32
    const float* phi = (const float*)d_in[1];  // [K,D,T] f32
    const int*   evt = (const int*)d_in[2];    // [N,D]   i32

    const long long PI_SZ  = (long long)N_ * D_ * T_;
    const long long TH_SZ  = (long long)N_ * K_ * T_;
    const long long PHP_SZ = (long long)K_ * D_ * T_;

    float* out   = (float*)d_out;
    float* pi    = out;
    float* theta = out + PI_SZ;
    float* phip  = out + PI_SZ + TH_SZ;

    const long long osz = (long long)out_size;
    if (osz < PI_SZ + TH_SZ)
        cudaGetSymbolAddress((void**)&theta, g_theta_scratch);
    if (osz < PI_SZ + TH_SZ + PHP_SZ)
        cudaGetSymbolAddress((void**)&phip, g_phip_scratch);

    // 1) phi_prob = sigmoid(phi)
    int nvec = (K_ * D_ * T_) / 4;
    sigmoid_kernel<<<(nvec + 255) / 256, 256>>>((const float4*)phi,
                                                (float4*)phip);

    // 2) theta = softmax(lambda)
    int npts = N_ * T_;
    softmax_kernel<<<(npts + 255) / 256, 256>>>(lam, theta);

    // 3) pi = mask*clip(theta @ phi_prob)
    cudaFuncSetAttribute(gemm_kernel,
                         cudaFuncAttributeMaxDynamicSharedMemorySize,
                         SMEM_BYTES);
    dim3 grid(D_ / DT, (T_ + TC - 1) / TC, ZSPLIT);  // 8 x 4 x 9 = 288
    gemm_kernel<<<grid, NTB, SMEM_BYTES>>>(theta, phip, evt, pi);
}